// round 3
// baseline (speedup 1.0000x reference)
#include <cuda_runtime.h>
#include <cstddef>

#define Bsz 64
#define Sq  512
#define Isz 512
#define Hsz 1024
#define G3  3072   // 3*Hsz

// Scratch (static device allocations are allowed; no cudaMalloc anywhere)
__device__ float g_xg[(size_t)Sq * Bsz * G3];   // x_gates, layout [s][b][g], g in 0..3071 (r|z|n)
__device__ float g_h[2][Bsz * Hsz];             // h ping-pong buffers

// ---------------------------------------------------------------------------
// Kernel 1: x_gates = inputs @ W_ih^T + bias_ih
//   A: inputs as [M=B*S][K=I] row-major (row m = (b = m>>9, s = m&511))
//   W: weight_ih [G3][I] row-major
//   Output written to g_xg in [s][b][g] layout.
// 128x128 tile, BK=16, 256 threads, 8x8 register micro-tile.
// ---------------------------------------------------------------------------
__global__ __launch_bounds__(256) void xgemm_kernel(
    const float* __restrict__ A,
    const float* __restrict__ W,
    const float* __restrict__ bias,
    float* __restrict__ xg)
{
    __shared__ float As[16][132];   // [k][m], padded
    __shared__ float Bs[16][132];   // [k][n], padded

    const int m0 = blockIdx.y * 128;
    const int n0 = blockIdx.x * 128;
    const int t  = threadIdx.x;
    const int tr = t >> 4;          // 0..15
    const int tc = t & 15;          // 0..15

    const int lrow = t >> 2;        // 0..63
    const int lk4  = (t & 3) * 4;   // 0,4,8,12

    float acc[8][8] = {};

    for (int k0 = 0; k0 < Isz; k0 += 16) {
        #pragma unroll
        for (int p = 0; p < 2; p++) {
            int mm = lrow + p * 64;
            float4 va = *(const float4*)(A + (size_t)(m0 + mm) * Isz + k0 + lk4);
            As[lk4 + 0][mm] = va.x; As[lk4 + 1][mm] = va.y;
            As[lk4 + 2][mm] = va.z; As[lk4 + 3][mm] = va.w;
            float4 vw = *(const float4*)(W + (size_t)(n0 + mm) * Isz + k0 + lk4);
            Bs[lk4 + 0][mm] = vw.x; Bs[lk4 + 1][mm] = vw.y;
            Bs[lk4 + 2][mm] = vw.z; Bs[lk4 + 3][mm] = vw.w;
        }
        __syncthreads();

        #pragma unroll
        for (int kk = 0; kk < 16; kk++) {
            float a[8], b[8];
            #pragma unroll
            for (int i = 0; i < 8; i++) a[i] = As[kk][tr * 8 + i];
            #pragma unroll
            for (int j = 0; j < 8; j++) b[j] = Bs[kk][tc * 8 + j];
            #pragma unroll
            for (int i = 0; i < 8; i++)
                #pragma unroll
                for (int j = 0; j < 8; j++)
                    acc[i][j] += a[i] * b[j];
        }
        __syncthreads();
    }

    // Epilogue: add bias, scatter to [s][b][g]
    float bv[8];
    #pragma unroll
    for (int j = 0; j < 8; j++) bv[j] = bias[n0 + tc * 8 + j];

    #pragma unroll
    for (int i = 0; i < 8; i++) {
        int m = m0 + tr * 8 + i;
        int s = m & (Sq - 1);
        int b = m >> 9;
        float* dst = xg + (size_t)s * (Bsz * G3) + (size_t)b * G3 + n0 + tc * 8;
        #pragma unroll
        for (int j = 0; j < 8; j++) dst[j] = acc[i][j] + bv[j];
    }
}

// ---------------------------------------------------------------------------
// Kernel 2: one fused GRU step.
//   r = sigmoid(xr + h@Whr^T + bhr)
//   z = sigmoid(xz + h@Whz^T + bhz)
//   n = tanh  (xn + r*(h@Whn^T + bhn))
//   h' = (1-z)*n + z*h
// Grid: 128 blocks (8 hidden columns each, all 64 batches, all 3 gates).
// 128 threads: thread = (b-group of 4) x (one j). 12 fp32 accumulators.
// ---------------------------------------------------------------------------
__global__ __launch_bounds__(128) void gru_step_kernel(
    const float* __restrict__ xg_s,   // [B][G3] for this step
    const float* __restrict__ h_in,   // [B][H]
    const float* __restrict__ Whh,    // [G3][H] row-major
    const float* __restrict__ bhh,    // [G3]
    float* __restrict__ h_out,        // [B][H]
    float* __restrict__ out_s)        // out + s*H; element (b,j) at b*S*H + j
{
    __shared__ float hs[64][65];      // [b][k-tile], padded (conflict-free inner reads)
    __shared__ float ws[24][65];      // rows: [g*8 + jj][k-tile]

    const int t  = threadIdx.x;
    const int j0 = blockIdx.x * 8;
    const int jj = t & 7;
    const int b0 = (t >> 3) * 4;      // 16 b-groups of 4

    float ar[4] = {}, az[4] = {}, an[4] = {};

    for (int k0 = 0; k0 < Hsz; k0 += 64) {
        // Load h tile: 64 x 64
        #pragma unroll
        for (int i = 0; i < 32; i++) {
            int idx = t + 128 * i;
            int k = idx & 63, b = idx >> 6;
            hs[b][k] = h_in[b * Hsz + k0 + k];
        }
        // Load W tile: 24 rows (3 gates x 8 j) x 64
        #pragma unroll
        for (int i = 0; i < 12; i++) {
            int idx = t + 128 * i;
            int k = idx & 63, row = idx >> 6;          // 0..23
            int g = row >> 3, jr = row & 7;
            ws[row][k] = Whh[(size_t)(g * Hsz + j0 + jr) * Hsz + k0 + k];
        }
        __syncthreads();

        #pragma unroll 8
        for (int kk = 0; kk < 64; kk++) {
            float wr = ws[jj][kk];
            float wz = ws[8  + jj][kk];
            float wn = ws[16 + jj][kk];
            #pragma unroll
            for (int i = 0; i < 4; i++) {
                float hv = hs[b0 + i][kk];
                ar[i] += hv * wr;
                az[i] += hv * wz;
                an[i] += hv * wn;
            }
        }
        __syncthreads();
    }

    const int j = j0 + jj;
    const float bhr = bhh[j];
    const float bhz = bhh[Hsz + j];
    const float bhn = bhh[2 * Hsz + j];

    #pragma unroll
    for (int i = 0; i < 4; i++) {
        int b = b0 + i;
        float xr = xg_s[(size_t)b * G3 + j];
        float xz = xg_s[(size_t)b * G3 + Hsz + j];
        float xn = xg_s[(size_t)b * G3 + 2 * Hsz + j];
        float hp = h_in[b * Hsz + j];

        float r = 1.f / (1.f + expf(-(xr + ar[i] + bhr)));
        float z = 1.f / (1.f + expf(-(xz + az[i] + bhz)));
        float n = tanhf(xn + r * (an[i] + bhn));
        float hn = (1.f - z) * n + z * hp;

        h_out[b * Hsz + j] = hn;
        out_s[(size_t)b * Sq * Hsz + j] = hn;
    }
}

// ---------------------------------------------------------------------------
// kernel_launch: graph-capturable (kernel launches + one async D2D memcpy).
// Inputs: 0 inputs[B,S,I], 1 h0[1,B,H], 2 weight_ih[3H,I], 3 weight_hh[3H,H],
//         4 bias_ih[3H], 5 bias_hh[3H].  Output: outputs[B,S,H] ++ hn[1,B,H].
// ---------------------------------------------------------------------------
extern "C" void kernel_launch(void* const* d_in, const int* in_sizes, int n_in,
                              void* d_out, int out_size)
{
    const float* inputs = (const float*)d_in[0];
    const float* h0     = (const float*)d_in[1];
    const float* Wih    = (const float*)d_in[2];
    const float* Whh    = (const float*)d_in[3];
    const float* bih    = (const float*)d_in[4];
    const float* bhh    = (const float*)d_in[5];
    float* out = (float*)d_out;

    float* xg   = nullptr;
    float* hbuf = nullptr;
    cudaGetSymbolAddress((void**)&xg, g_xg);
    cudaGetSymbolAddress((void**)&hbuf, g_h);

    // Phase A: all input projections in one GEMM
    dim3 ggrid(G3 / 128, (Bsz * Sq) / 128);   // (24, 256)
    xgemm_kernel<<<ggrid, 256>>>(inputs, Wih, bih, xg);

    // Phase B: sequential scan, one fused kernel per step
    for (int s = 0; s < Sq; s++) {
        const float* h_in = (s == 0) ? h0 : (hbuf + (size_t)(s & 1) * Bsz * Hsz);
        float* h_out = hbuf + (size_t)((s + 1) & 1) * Bsz * Hsz;
        gru_step_kernel<<<Hsz / 8, 128>>>(
            xg + (size_t)s * Bsz * G3,
            h_in, Whh, bhh, h_out,
            out + (size_t)s * Hsz);
    }

    // hn = final h (after step 511 it lives in buffer ((511+1)&1) = 0)
    cudaMemcpyAsync(out + (size_t)Bsz * Sq * Hsz, hbuf,
                    (size_t)Bsz * Hsz * sizeof(float),
                    cudaMemcpyDeviceToDevice);
}